// round 15
// baseline (speedup 1.0000x reference)
#include <cuda_runtime.h>
#include <cuda_fp16.h>
#include <cstdint>

#define NNODES 50000
#define NEDGES 800000
#define CDIM 256
#define FIN 768

#define BM 128
#define BN 128
#define KCH 32                    // halfs per K-chunk (2 MMA steps of k16)
#define PITCH 20                  // uints (half2 pairs) per row; conflict-free
#define BUFB (BM * PITCH * 4)     // bytes per stage buffer (10240)

// x-conversion/GEMM1 pipeline partition (rows)
#define P0 12800
#define P1 12800
#define P2 12800
#define P3 (NNODES - P0 - P1 - P2)   // 11600

// Scratch (allocation-free rule: device globals)
__device__ float  g_dinv[NNODES];
__device__ int    g_deg[NNODES];
__device__ int    g_off[NNODES + 1];
__device__ int    g_cur[NNODES];
__device__ int    g_csrc[NEDGES];
__device__ __half g_xh [NNODES * FIN];   // x converted to fp16
__device__ __half g_hsh[NNODES * CDIM];  // GEMM output h, fp16 (gather payload)
__device__ __half g_h1h[NNODES * CDIM];  // layer-1 activation, fp16
__device__ __half g_WT1[CDIM * FIN];     // W1^T fp16
__device__ __half g_WT2[CDIM * CDIM];    // W2^T fp16

__device__ __forceinline__ uint32_t smem_u32(const void* p) {
    uint32_t a;
    asm("{ .reg .u64 t; cvta.to.shared.u64 t, %1; cvt.u32.u64 %0, t; }"
        : "=r"(a) : "l"(p));
    return a;
}
__device__ __forceinline__ void mma_f16(float* c, const uint32_t* a, const uint32_t* b) {
    asm volatile(
        "mma.sync.aligned.m16n8k16.row.col.f32.f16.f16.f32 "
        "{%0,%1,%2,%3}, {%4,%5,%6,%7}, {%8,%9}, {%0,%1,%2,%3};"
        : "+f"(c[0]), "+f"(c[1]), "+f"(c[2]), "+f"(c[3])
        : "r"(a[0]), "r"(a[1]), "r"(a[2]), "r"(a[3]), "r"(b[0]), "r"(b[1]));
}

// ---------------------------------------------------------------------------
__global__ void zero_int_k(int* __restrict__ p, int n) {
    int i = blockIdx.x * blockDim.x + threadIdx.x;
    if (i < n) p[i] = 0;
}
__global__ void degree_k(const int* __restrict__ dst, int E4) {
    int i = blockIdx.x * blockDim.x + threadIdx.x;
    if (i < E4) {
        int4 d = reinterpret_cast<const int4*>(dst)[i];
        atomicAdd(&g_deg[d.x], 1);
        atomicAdd(&g_deg[d.y], 1);
        atomicAdd(&g_deg[d.z], 1);
        atomicAdd(&g_deg[d.w], 1);
    }
}
__global__ void dinv_k(int n) {
    int i = blockIdx.x * blockDim.x + threadIdx.x;
    if (i < n) g_dinv[i] = rsqrtf((float)g_deg[i] + 1.0f);  // +1 = self loop
}

__global__ void scan_k() {
    __shared__ int sums[1024];
    const int T = 1024;
    const int chunk = (NNODES + T - 1) / T;
    int t = threadIdx.x;
    int base = t * chunk;
    int s = 0;
    for (int j = 0; j < chunk; j++) {
        int i = base + j;
        if (i < NNODES) s += g_deg[i];
    }
    sums[t] = s;
    __syncthreads();
    for (int d = 1; d < T; d <<= 1) {
        int v = (t >= d) ? sums[t - d] : 0;
        __syncthreads();
        sums[t] += v;
        __syncthreads();
    }
    int run = (t == 0) ? 0 : sums[t - 1];
    for (int j = 0; j < chunk; j++) {
        int i = base + j;
        if (i < NNODES) {
            g_off[i] = run;
            g_cur[i] = run;
            run += g_deg[i];
        }
    }
    if (t == T - 1) g_off[NNODES] = run;
}

__global__ void csr_fill_k(const int* __restrict__ src,
                           const int* __restrict__ dst, int E) {
    int e = blockIdx.x * blockDim.x + threadIdx.x;
    if (e < E) {
        int p = atomicAdd(&g_cur[dst[e]], 1);
        g_csrc[p] = src[e];
    }
}

// Weight transposes to fp16 (both in one launch).
#define PREP_W (FIN * CDIM + CDIM * CDIM)        // 262144
__global__ void prep_w_k(const float* __restrict__ W1,
                         const float* __restrict__ W2) {
    int idx = blockIdx.x * blockDim.x + threadIdx.x;
    if (idx < FIN * CDIM) {
        int n = idx & (CDIM - 1);
        int k = idx >> 8;
        g_WT1[(size_t)n * FIN + k] = __float2half_rn(W1[(size_t)k * CDIM + n]);
    } else if (idx < PREP_W) {
        int i = idx - FIN * CDIM;
        int n = i & (CDIM - 1);
        int k = i >> 8;
        g_WT2[(size_t)n * CDIM + k] = __float2half_rn(W2[(size_t)k * CDIM + n]);
    }
}

// Convert rows [r0, r0+nr) of x to fp16.
__global__ void prep_x_k(const float* __restrict__ x, int r0, int nr) {
    int i = blockIdx.x * blockDim.x + threadIdx.x;
    int n4 = nr * (FIN / 4);
    if (i < n4) {
        size_t g = (size_t)r0 * (FIN / 4) + i;
        float4 v = reinterpret_cast<const float4*>(x)[g];
        __half2 h01 = __floats2half2_rn(v.x, v.y);
        __half2 h23 = __floats2half2_rn(v.z, v.w);
        uint2 u;
        u.x = *reinterpret_cast<uint32_t*>(&h01);
        u.y = *reinterpret_cast<uint32_t*>(&h23);
        reinterpret_cast<uint2*>(g_xh)[g] = u;
    }
}

// ---------------------------------------------------------------------------
// Ch[M,256](fp16) = A[M,K](fp16) @ WT^T(fp16), fp32 accumulate.
// 128x128 CTA tile, 8 warps (2x4), 64x32 warp tiles, cp.async 2-stage,
// mma.m16n8k16.
// ---------------------------------------------------------------------------
__global__ __launch_bounds__(256, 2) void gemm_mma_k(
    const __half* __restrict__ A, const __half* __restrict__ WT,
    __half* __restrict__ Ch, int M, int K)
{
    __shared__ uint32_t As[2][BM * PITCH];
    __shared__ uint32_t Bs[2][BN * PITCH];

    const int tid  = threadIdx.x;
    const int lane = tid & 31;
    const int wid  = tid >> 5;
    const int wm   = wid & 1;
    const int wn   = wid >> 1;
    const int gq   = lane >> 2;
    const int cq   = lane & 3;
    const int row0 = blockIdx.y * BM;
    const int col0 = blockIdx.x * BN;

    const uint32_t asb = smem_u32(&As[0][0]);
    const uint32_t bsb = smem_u32(&Bs[0][0]);

    float acc[4][4][4];
    #pragma unroll
    for (int mt = 0; mt < 4; mt++)
        #pragma unroll
        for (int nt = 0; nt < 4; nt++)
            #pragma unroll
            for (int q = 0; q < 4; q++) acc[mt][nt][q] = 0.f;

    const int nkc = K / KCH;

    auto issue = [&](int kc, int buf) {
        const int koff = kc * KCH;               // in halfs
        #pragma unroll
        for (int t = 0; t < 2; t++) {
            int idx = tid + t * 256;             // 0..511 16B chunks
            int r   = idx >> 2;                  // row 0..127
            int c16 = idx & 3;                   // chunk within row
            uint32_t soff = (uint32_t)(r * (PITCH * 4) + c16 * 16) + (uint32_t)buf * BUFB;
            int gr = row0 + r;
            const __half* srcA = A + (size_t)(gr < M ? gr : M - 1) * K + koff + c16 * 8;
            int nb = (gr < M) ? 16 : 0;
            asm volatile("cp.async.ca.shared.global [%0], [%1], 16, %2;"
                         :: "r"(asb + soff), "l"(srcA), "r"(nb));
            const __half* srcB = WT + (size_t)(col0 + r) * K + koff + c16 * 8;
            asm volatile("cp.async.ca.shared.global [%0], [%1], 16;"
                         :: "r"(bsb + soff), "l"(srcB));
        }
        asm volatile("cp.async.commit_group;" ::: "memory");
    };

    issue(0, 0);

    for (int kc = 0; kc < nkc; kc++) {
        const int cur = kc & 1;
        const bool more = (kc + 1) < nkc;
        if (more) {
            issue(kc + 1, cur ^ 1);
            asm volatile("cp.async.wait_group 1;" ::: "memory");
        } else {
            asm volatile("cp.async.wait_group 0;" ::: "memory");
        }
        __syncthreads();

        #pragma unroll
        for (int k0 = 0; k0 < 16; k0 += 8) {     // 2 k16 steps
            uint32_t bf[4][2];
            #pragma unroll
            for (int nt = 0; nt < 4; nt++) {
                int n = wn * 32 + nt * 8 + gq;
                bf[nt][0] = Bs[cur][n * PITCH + k0 + cq];
                bf[nt][1] = Bs[cur][n * PITCH + k0 + cq + 4];
            }
            #pragma unroll
            for (int mt = 0; mt < 4; mt++) {
                int r = wm * 64 + mt * 16 + gq;
                uint32_t af[4];
                af[0] = As[cur][(r    ) * PITCH + k0 + cq    ];
                af[1] = As[cur][(r + 8) * PITCH + k0 + cq    ];
                af[2] = As[cur][(r    ) * PITCH + k0 + cq + 4];
                af[3] = As[cur][(r + 8) * PITCH + k0 + cq + 4];
                #pragma unroll
                for (int nt = 0; nt < 4; nt++)
                    mma_f16(acc[mt][nt], af, bf[nt]);
            }
        }
        __syncthreads();
    }

    // epilogue: store fp16
    #pragma unroll
    for (int mt = 0; mt < 4; mt++) {
        #pragma unroll
        for (int h = 0; h < 2; h++) {
            int row = row0 + wm * 64 + mt * 16 + gq + h * 8;
            if (row < M) {
                __half* cp = Ch + (size_t)row * CDIM + col0 + wn * 32;
                #pragma unroll
                for (int nt = 0; nt < 4; nt++) {
                    __half2 o = __floats2half2_rn(acc[mt][nt][h * 2 + 0],
                                                  acc[mt][nt][h * 2 + 1]);
                    *reinterpret_cast<__half2*>(cp + nt * 8 + cq * 2) = o;
                }
            }
        }
    }
}

// ---------------------------------------------------------------------------
// Fused CSR gather: ONE WARP per node, uint4 (8 halfs) per lane = full row.
// 8-edge unroll -> 8 outstanding LDG.128 per lane (MLP 8). fp32 accumulate.
// ---------------------------------------------------------------------------
__device__ __forceinline__ void acc_row(float* acc, uint4 u, float d) {
    float2 f0 = __half22float2(*reinterpret_cast<__half2*>(&u.x));
    float2 f1 = __half22float2(*reinterpret_cast<__half2*>(&u.y));
    float2 f2 = __half22float2(*reinterpret_cast<__half2*>(&u.z));
    float2 f3 = __half22float2(*reinterpret_cast<__half2*>(&u.w));
    acc[0] = fmaf(f0.x, d, acc[0]); acc[1] = fmaf(f0.y, d, acc[1]);
    acc[2] = fmaf(f1.x, d, acc[2]); acc[3] = fmaf(f1.y, d, acc[3]);
    acc[4] = fmaf(f2.x, d, acc[4]); acc[5] = fmaf(f2.y, d, acc[5]);
    acc[6] = fmaf(f3.x, d, acc[6]); acc[7] = fmaf(f3.y, d, acc[7]);
}

__global__ __launch_bounds__(256) void agg_k(const float* __restrict__ b,
                                             void* __restrict__ outp,
                                             int half_out)
{
    int node = blockIdx.x * 8 + (threadIdx.x >> 5);   // warp per node
    if (node >= NNODES) return;
    int lane = threadIdx.x & 31;

    const uint4* hs4 = reinterpret_cast<const uint4*>(g_hsh);  // 32 uint4/row
    float di = g_dinv[node];

    float acc[8];
    #pragma unroll
    for (int q = 0; q < 8; q++) acc[q] = 0.f;
    acc_row(acc, hs4[(size_t)node * 32 + lane], di);           // self loop

    int j   = g_off[node];
    int end = g_off[node + 1];
    for (; j + 7 < end; j += 8) {
        int   e[8];
        float d[8];
        uint4 u[8];
        #pragma unroll
        for (int q = 0; q < 8; q++) e[q] = g_csrc[j + q];
        #pragma unroll
        for (int q = 0; q < 8; q++) d[q] = g_dinv[e[q]];
        #pragma unroll
        for (int q = 0; q < 8; q++) u[q] = hs4[(size_t)e[q] * 32 + lane];
        #pragma unroll
        for (int q = 0; q < 8; q++) acc_row(acc, u[q], d[q]);
    }
    for (; j + 3 < end; j += 4) {
        int   e[4];
        float d[4];
        uint4 u[4];
        #pragma unroll
        for (int q = 0; q < 4; q++) e[q] = g_csrc[j + q];
        #pragma unroll
        for (int q = 0; q < 4; q++) d[q] = g_dinv[e[q]];
        #pragma unroll
        for (int q = 0; q < 4; q++) u[q] = hs4[(size_t)e[q] * 32 + lane];
        #pragma unroll
        for (int q = 0; q < 4; q++) acc_row(acc, u[q], d[q]);
    }
    for (; j < end; j++) {
        int e0 = g_csrc[j];
        acc_row(acc, hs4[(size_t)e0 * 32 + lane], g_dinv[e0]);
    }

    const float4 b0 = *reinterpret_cast<const float4*>(b + lane * 8);
    const float4 b1 = *reinterpret_cast<const float4*>(b + lane * 8 + 4);
    float o[8];
    o[0] = fmaf(acc[0], di, b0.x); o[1] = fmaf(acc[1], di, b0.y);
    o[2] = fmaf(acc[2], di, b0.z); o[3] = fmaf(acc[3], di, b0.w);
    o[4] = fmaf(acc[4], di, b1.x); o[5] = fmaf(acc[5], di, b1.y);
    o[6] = fmaf(acc[6], di, b1.z); o[7] = fmaf(acc[7], di, b1.w);

    if (half_out) {
        #pragma unroll
        for (int q = 0; q < 8; q++) o[q] = fmaxf(o[q], 0.f);
        __half2 h0 = __floats2half2_rn(o[0], o[1]);
        __half2 h1 = __floats2half2_rn(o[2], o[3]);
        __half2 h2 = __floats2half2_rn(o[4], o[5]);
        __half2 h3 = __floats2half2_rn(o[6], o[7]);
        uint4 u;
        u.x = *reinterpret_cast<uint32_t*>(&h0);
        u.y = *reinterpret_cast<uint32_t*>(&h1);
        u.z = *reinterpret_cast<uint32_t*>(&h2);
        u.w = *reinterpret_cast<uint32_t*>(&h3);
        reinterpret_cast<uint4*>(outp)[(size_t)node * 32 + lane] = u;
    } else {
        float4* op = reinterpret_cast<float4*>(outp) + (size_t)node * 64 + lane * 2;
        op[0] = make_float4(o[0], o[1], o[2], o[3]);
        op[1] = make_float4(o[4], o[5], o[6], o[7]);
    }
}

// ---------------------------------------------------------------------------
extern "C" void kernel_launch(void* const* d_in, const int* in_sizes, int n_in,
                              void* d_out, int out_size)
{
    const float* x  = (const float*)d_in[0];
    const int*   ei = (const int*)  d_in[1];
    const float* W1 = (const float*)d_in[2];
    const float* b1 = (const float*)d_in[3];
    const float* W2 = (const float*)d_in[4];
    const float* b2 = (const float*)d_in[5];
    (void)in_sizes; (void)n_in; (void)out_size;

    const int* src = ei;
    const int* dst = ei + NEDGES;

    __half *xh, *hsh, *h1h, *wt1, *wt2;
    int* degp;
    cudaGetSymbolAddress((void**)&xh,  g_xh);
    cudaGetSymbolAddress((void**)&hsh, g_hsh);
    cudaGetSymbolAddress((void**)&h1h, g_h1h);
    cudaGetSymbolAddress((void**)&wt1, g_WT1);
    cudaGetSymbolAddress((void**)&wt2, g_WT2);
    cudaGetSymbolAddress((void**)&degp, g_deg);

    // Streams + events for fork/join inside graph capture.
    static cudaStream_t sB = nullptr, sC = nullptr;
    static cudaEvent_t evFork = nullptr, evJoin = nullptr;
    static cudaEvent_t evX[3] = {nullptr, nullptr, nullptr};
    if (!sB) {
        cudaStreamCreateWithFlags(&sB, cudaStreamNonBlocking);
        cudaStreamCreateWithFlags(&sC, cudaStreamNonBlocking);
        cudaEventCreateWithFlags(&evFork, cudaEventDisableTiming);
        cudaEventCreateWithFlags(&evJoin, cudaEventDisableTiming);
        for (int i = 0; i < 3; i++)
            cudaEventCreateWithFlags(&evX[i], cudaEventDisableTiming);
    }

    const int parts[4] = {P0, P1, P2, P3};
    const int pbase[4] = {0, P0, P0 + P1, P0 + P1 + P2};
    const int agg_grid = (NNODES + 7) / 8;

    // Fork side streams off the main (capturing) stream.
    cudaEventRecord(evFork, 0);
    cudaStreamWaitEvent(sB, evFork, 0);
    cudaStreamWaitEvent(sC, evFork, 0);

    auto px_grid = [](int nr) { return (nr * (FIN / 4) + 255) / 256; };

    // Main: weights + x-part0 + GEMM1 parts.  sB: CSR.  sC: x-parts 1..3.
    prep_w_k<<<(PREP_W + 255) / 256, 256>>>(W1, W2);                           // 0 main
    prep_x_k<<<px_grid(P0), 256>>>(x, 0, P0);                                  // 1 main
    zero_int_k<<<(NNODES + 255) / 256, 256, 0, sB>>>(degp, NNODES);            // 2 side
    {   // GEMM1 part 0  (4th launch call -> ncu capture slot)
        dim3 g(CDIM / BN, (P0 + BM - 1) / BM);
        gemm_mma_k<<<g, 256>>>(xh, wt1, hsh, P0, FIN);                         // 3 main <- ncu
    }
    // x-parts 1..3 on sC, each gating its GEMM1 part on main.
    for (int i = 1; i < 4; i++) {
        prep_x_k<<<px_grid(parts[i]), 256, 0, sC>>>(x, pbase[i], parts[i]);
        cudaEventRecord(evX[i - 1], sC);
    }
    degree_k<<<(NEDGES / 4 + 255) / 256, 256, 0, sB>>>(dst, NEDGES / 4);
    dinv_k  <<<(NNODES + 255) / 256, 256, 0, sB>>>(NNODES);
    scan_k  <<<1, 1024, 0, sB>>>();
    csr_fill_k<<<(NEDGES + 255) / 256, 256, 0, sB>>>(src, dst, NEDGES);

    for (int i = 1; i < 4; i++) {
        cudaStreamWaitEvent(0, evX[i - 1], 0);
        dim3 g(CDIM / BN, (parts[i] + BM - 1) / BM);
        gemm_mma_k<<<g, 256>>>(xh + (size_t)pbase[i] * FIN, wt1,
                               hsh + (size_t)pbase[i] * CDIM, parts[i], FIN);
    }

    // Join: agg1 needs CSR + dinv + full hsh.
    cudaEventRecord(evJoin, sB);
    cudaStreamWaitEvent(0, evJoin, 0);

    agg_k<<<agg_grid, 256>>>(b1, h1h, 1);
    {
        dim3 g(CDIM / BN, (NNODES + BM - 1) / BM);
        gemm_mma_k<<<g, 256>>>(h1h, wt2, hsh, NNODES, CDIM);
    }
    agg_k<<<agg_grid, 256>>>(b2, d_out, 0);
}

// round 16
// speedup vs baseline: 1.1766x; 1.1766x over previous
#include <cuda_runtime.h>
#include <cuda_fp16.h>
#include <cstdint>

#define NNODES 50000
#define NEDGES 800000
#define CDIM 256
#define FIN 768

#define BM 128
#define BN 128
#define KCH 32                    // elements (halfs/floats) per K-chunk
#define PITCH 20                  // uints (half2 pairs) per row; conflict-free
#define BUFB (BM * PITCH * 4)     // bytes per stage buffer (10240)

// Scratch (allocation-free rule: device globals)
__device__ float  g_dinv[NNODES];
__device__ int    g_deg[NNODES];
__device__ int    g_off[NNODES + 1];
__device__ int    g_cur[NNODES];
__device__ int    g_csrc[NEDGES];
__device__ __half g_hsh[NNODES * CDIM];  // GEMM output h, fp16 (gather payload)
__device__ __half g_h1h[NNODES * CDIM];  // layer-1 activation, fp16
__device__ __half g_WT1[CDIM * FIN];     // W1^T fp16
__device__ __half g_WT2[CDIM * CDIM];    // W2^T fp16

__device__ __forceinline__ uint32_t smem_u32(const void* p) {
    uint32_t a;
    asm("{ .reg .u64 t; cvta.to.shared.u64 t, %1; cvt.u32.u64 %0, t; }"
        : "=r"(a) : "l"(p));
    return a;
}
__device__ __forceinline__ void mma_f16(float* c, const uint32_t* a, const uint32_t* b) {
    asm volatile(
        "mma.sync.aligned.m16n8k16.row.col.f32.f16.f16.f32 "
        "{%0,%1,%2,%3}, {%4,%5,%6,%7}, {%8,%9}, {%0,%1,%2,%3};"
        : "+f"(c[0]), "+f"(c[1]), "+f"(c[2]), "+f"(c[3])
        : "r"(a[0]), "r"(a[1]), "r"(a[2]), "r"(a[3]), "r"(b[0]), "r"(b[1]));
}

// ---------------------------------------------------------------------------
__global__ void zero_int_k(int* __restrict__ p, int n) {
    int i = blockIdx.x * blockDim.x + threadIdx.x;
    if (i < n) p[i] = 0;
}
__global__ void degree_k(const int* __restrict__ dst, int E4) {
    int i = blockIdx.x * blockDim.x + threadIdx.x;
    if (i < E4) {
        int4 d = reinterpret_cast<const int4*>(dst)[i];
        atomicAdd(&g_deg[d.x], 1);
        atomicAdd(&g_deg[d.y], 1);
        atomicAdd(&g_deg[d.z], 1);
        atomicAdd(&g_deg[d.w], 1);
    }
}
__global__ void dinv_k(int n) {
    int i = blockIdx.x * blockDim.x + threadIdx.x;
    if (i < n) g_dinv[i] = rsqrtf((float)g_deg[i] + 1.0f);  // +1 = self loop
}

__global__ void scan_k() {
    __shared__ int sums[1024];
    const int T = 1024;
    const int chunk = (NNODES + T - 1) / T;
    int t = threadIdx.x;
    int base = t * chunk;
    int s = 0;
    for (int j = 0; j < chunk; j++) {
        int i = base + j;
        if (i < NNODES) s += g_deg[i];
    }
    sums[t] = s;
    __syncthreads();
    for (int d = 1; d < T; d <<= 1) {
        int v = (t >= d) ? sums[t - d] : 0;
        __syncthreads();
        sums[t] += v;
        __syncthreads();
    }
    int run = (t == 0) ? 0 : sums[t - 1];
    for (int j = 0; j < chunk; j++) {
        int i = base + j;
        if (i < NNODES) {
            g_off[i] = run;
            g_cur[i] = run;
            run += g_deg[i];
        }
    }
    if (t == T - 1) g_off[NNODES] = run;
}

__global__ void csr_fill_k(const int* __restrict__ src,
                           const int* __restrict__ dst, int E) {
    int e = blockIdx.x * blockDim.x + threadIdx.x;
    if (e < E) {
        int p = atomicAdd(&g_cur[dst[e]], 1);
        g_csrc[p] = src[e];
    }
}

// Weight transposes to fp16 (both in one launch).
#define PREP_W (FIN * CDIM + CDIM * CDIM)        // 262144
__global__ void prep_w_k(const float* __restrict__ W1,
                         const float* __restrict__ W2) {
    int idx = blockIdx.x * blockDim.x + threadIdx.x;
    if (idx < FIN * CDIM) {
        int n = idx & (CDIM - 1);
        int k = idx >> 8;
        g_WT1[(size_t)n * FIN + k] = __float2half_rn(W1[(size_t)k * CDIM + n]);
    } else if (idx < PREP_W) {
        int i = idx - FIN * CDIM;
        int n = i & (CDIM - 1);
        int k = i >> 8;
        g_WT2[(size_t)n * CDIM + k] = __float2half_rn(W2[(size_t)k * CDIM + n]);
    }
}

// ---------------------------------------------------------------------------
// Ch[M,256](fp16) = A[M,K] @ WT^T(fp16), fp32 accumulate.  mma.m16n8k16.
// AF32=true : A is fp32 (x read directly); chunks staged through registers,
//             converted to fp16 at STS time -> identical smem layout/mainloop.
// AF32=false: A is fp16; cp.async.
// 128x128 CTA tile, 8 warps (2x4), 64x32 warp tiles, 2-stage pipeline.
// ---------------------------------------------------------------------------
template <bool AF32>
__global__ __launch_bounds__(256, 2) void gemm_mma_k(
    const void* __restrict__ Ap, const __half* __restrict__ WT,
    __half* __restrict__ Ch, int M, int K)
{
    __shared__ uint32_t As[2][BM * PITCH];
    __shared__ uint32_t Bs[2][BN * PITCH];

    const int tid  = threadIdx.x;
    const int lane = tid & 31;
    const int wid  = tid >> 5;
    const int wm   = wid & 1;
    const int wn   = wid >> 1;
    const int gq   = lane >> 2;
    const int cq   = lane & 3;
    const int row0 = blockIdx.y * BM;
    const int col0 = blockIdx.x * BN;

    const uint32_t asb = smem_u32(&As[0][0]);
    const uint32_t bsb = smem_u32(&Bs[0][0]);

    float acc[4][4][4];
    #pragma unroll
    for (int mt = 0; mt < 4; mt++)
        #pragma unroll
        for (int nt = 0; nt < 4; nt++)
            #pragma unroll
            for (int q = 0; q < 4; q++) acc[mt][nt][q] = 0.f;

    const int nkc = K / KCH;
    float4 areg[4];                               // AF32 staging (16 regs)

    // Load A chunk kc (fp32) into registers.
    auto loadA = [&](int kc) {
        if (!AF32) return;
        const float* A = (const float*)Ap;
        #pragma unroll
        for (int t = 0; t < 4; t++) {
            int idx = tid + t * 256;              // 0..1023 float4s
            int r   = idx >> 3;                   // row 0..127
            int c4  = idx & 7;                    // float4 within 32-float row
            int gr  = row0 + r;
            areg[t] = (gr < M)
                ? *reinterpret_cast<const float4*>(A + (size_t)gr * K + kc * KCH + c4 * 4)
                : make_float4(0.f, 0.f, 0.f, 0.f);
        }
    };

    // Stage chunk kc into buffer buf: A (regs->cvt->STS | cp.async), B cp.async.
    auto stage = [&](int kc, int buf) {
        if (AF32) {
            #pragma unroll
            for (int t = 0; t < 4; t++) {
                int idx = tid + t * 256;
                int r   = idx >> 3;
                int c4  = idx & 7;
                __half2 h0 = __floats2half2_rn(areg[t].x, areg[t].y);
                __half2 h1 = __floats2half2_rn(areg[t].z, areg[t].w);
                uint2 u;
                u.x = *reinterpret_cast<uint32_t*>(&h0);
                u.y = *reinterpret_cast<uint32_t*>(&h1);
                *reinterpret_cast<uint2*>(&As[buf][r * PITCH + c4 * 2]) = u;
            }
        } else {
            const __half* A = (const __half*)Ap;
            #pragma unroll
            for (int t = 0; t < 2; t++) {
                int idx = tid + t * 256;
                int r   = idx >> 2;
                int c16 = idx & 3;
                uint32_t soff = (uint32_t)(r * (PITCH * 4) + c16 * 16) + (uint32_t)buf * BUFB;
                int gr = row0 + r;
                const __half* srcA = A + (size_t)(gr < M ? gr : M - 1) * K + kc * KCH + c16 * 8;
                int nb = (gr < M) ? 16 : 0;
                asm volatile("cp.async.ca.shared.global [%0], [%1], 16, %2;"
                             :: "r"(asb + soff), "l"(srcA), "r"(nb));
            }
        }
        #pragma unroll
        for (int t = 0; t < 2; t++) {
            int idx = tid + t * 256;
            int r   = idx >> 2;
            int c16 = idx & 3;
            uint32_t soff = (uint32_t)(r * (PITCH * 4) + c16 * 16) + (uint32_t)buf * BUFB;
            const __half* srcB = WT + (size_t)(col0 + r) * K + kc * KCH + c16 * 8;
            asm volatile("cp.async.ca.shared.global [%0], [%1], 16;"
                         :: "r"(bsb + soff), "l"(srcB));
        }
        asm volatile("cp.async.commit_group;" ::: "memory");
    };

    // Prologue: stage chunks 0,1; prefetch regs for chunk 2.
    loadA(0);
    stage(0, 0);
    if (nkc > 1) { loadA(1); stage(1, 1); }
    if (nkc > 2) loadA(2);

    for (int kc = 0; kc < nkc; kc++) {
        const int cur = kc & 1;
        if (kc + 1 < nkc)
            asm volatile("cp.async.wait_group 1;" ::: "memory");
        else
            asm volatile("cp.async.wait_group 0;" ::: "memory");
        __syncthreads();

        #pragma unroll
        for (int k0 = 0; k0 < 16; k0 += 8) {     // 2 k16 steps
            uint32_t bf[4][2];
            #pragma unroll
            for (int nt = 0; nt < 4; nt++) {
                int n = wn * 32 + nt * 8 + gq;
                bf[nt][0] = Bs[cur][n * PITCH + k0 + cq];
                bf[nt][1] = Bs[cur][n * PITCH + k0 + cq + 4];
            }
            #pragma unroll
            for (int mt = 0; mt < 4; mt++) {
                int r = wm * 64 + mt * 16 + gq;
                uint32_t af[4];
                af[0] = As[cur][(r    ) * PITCH + k0 + cq    ];
                af[1] = As[cur][(r + 8) * PITCH + k0 + cq    ];
                af[2] = As[cur][(r    ) * PITCH + k0 + cq + 4];
                af[3] = As[cur][(r + 8) * PITCH + k0 + cq + 4];
                #pragma unroll
                for (int nt = 0; nt < 4; nt++)
                    mma_f16(acc[mt][nt], af, bf[nt]);
            }
        }
        __syncthreads();

        if (kc + 2 < nkc) {
            stage(kc + 2, cur);                  // buf cur free after barrier
            if (kc + 3 < nkc) loadA(kc + 3);
        }
    }

    // epilogue: store fp16
    #pragma unroll
    for (int mt = 0; mt < 4; mt++) {
        #pragma unroll
        for (int h = 0; h < 2; h++) {
            int row = row0 + wm * 64 + mt * 16 + gq + h * 8;
            if (row < M) {
                __half* cp = Ch + (size_t)row * CDIM + col0 + wn * 32;
                #pragma unroll
                for (int nt = 0; nt < 4; nt++) {
                    __half2 o = __floats2half2_rn(acc[mt][nt][h * 2 + 0],
                                                  acc[mt][nt][h * 2 + 1]);
                    *reinterpret_cast<__half2*>(cp + nt * 8 + cq * 2) = o;
                }
            }
        }
    }
}

// ---------------------------------------------------------------------------
// Fused CSR gather: ONE WARP per node, uint4 (8 halfs) per lane = full row.
// 8-edge unroll -> MLP 8. fp32 accumulate.
// ---------------------------------------------------------------------------
__device__ __forceinline__ void acc_row(float* acc, uint4 u, float d) {
    float2 f0 = __half22float2(*reinterpret_cast<__half2*>(&u.x));
    float2 f1 = __half22float2(*reinterpret_cast<__half2*>(&u.y));
    float2 f2 = __half22float2(*reinterpret_cast<__half2*>(&u.z));
    float2 f3 = __half22float2(*reinterpret_cast<__half2*>(&u.w));
    acc[0] = fmaf(f0.x, d, acc[0]); acc[1] = fmaf(f0.y, d, acc[1]);
    acc[2] = fmaf(f1.x, d, acc[2]); acc[3] = fmaf(f1.y, d, acc[3]);
    acc[4] = fmaf(f2.x, d, acc[4]); acc[5] = fmaf(f2.y, d, acc[5]);
    acc[6] = fmaf(f3.x, d, acc[6]); acc[7] = fmaf(f3.y, d, acc[7]);
}

__global__ __launch_bounds__(256) void agg_k(const float* __restrict__ b,
                                             void* __restrict__ outp,
                                             int half_out)
{
    int node = blockIdx.x * 8 + (threadIdx.x >> 5);   // warp per node
    if (node >= NNODES) return;
    int lane = threadIdx.x & 31;

    const uint4* hs4 = reinterpret_cast<const uint4*>(g_hsh);  // 32 uint4/row
    float di = g_dinv[node];

    float acc[8];
    #pragma unroll
    for (int q = 0; q < 8; q++) acc[q] = 0.f;
    acc_row(acc, hs4[(size_t)node * 32 + lane], di);           // self loop

    int j   = g_off[node];
    int end = g_off[node + 1];
    for (; j + 7 < end; j += 8) {
        int   e[8];
        float d[8];
        uint4 u[8];
        #pragma unroll
        for (int q = 0; q < 8; q++) e[q] = g_csrc[j + q];
        #pragma unroll
        for (int q = 0; q < 8; q++) d[q] = g_dinv[e[q]];
        #pragma unroll
        for (int q = 0; q < 8; q++) u[q] = hs4[(size_t)e[q] * 32 + lane];
        #pragma unroll
        for (int q = 0; q < 8; q++) acc_row(acc, u[q], d[q]);
    }
    for (; j + 3 < end; j += 4) {
        int   e[4];
        float d[4];
        uint4 u[4];
        #pragma unroll
        for (int q = 0; q < 4; q++) e[q] = g_csrc[j + q];
        #pragma unroll
        for (int q = 0; q < 4; q++) d[q] = g_dinv[e[q]];
        #pragma unroll
        for (int q = 0; q < 4; q++) u[q] = hs4[(size_t)e[q] * 32 + lane];
        #pragma unroll
        for (int q = 0; q < 4; q++) acc_row(acc, u[q], d[q]);
    }
    for (; j < end; j++) {
        int e0 = g_csrc[j];
        acc_row(acc, hs4[(size_t)e0 * 32 + lane], g_dinv[e0]);
    }

    const float4 b0 = *reinterpret_cast<const float4*>(b + lane * 8);
    const float4 b1 = *reinterpret_cast<const float4*>(b + lane * 8 + 4);
    float o[8];
    o[0] = fmaf(acc[0], di, b0.x); o[1] = fmaf(acc[1], di, b0.y);
    o[2] = fmaf(acc[2], di, b0.z); o[3] = fmaf(acc[3], di, b0.w);
    o[4] = fmaf(acc[4], di, b1.x); o[5] = fmaf(acc[5], di, b1.y);
    o[6] = fmaf(acc[6], di, b1.z); o[7] = fmaf(acc[7], di, b1.w);

    if (half_out) {
        #pragma unroll
        for (int q = 0; q < 8; q++) o[q] = fmaxf(o[q], 0.f);
        __half2 h0 = __floats2half2_rn(o[0], o[1]);
        __half2 h1 = __floats2half2_rn(o[2], o[3]);
        __half2 h2 = __floats2half2_rn(o[4], o[5]);
        __half2 h3 = __floats2half2_rn(o[6], o[7]);
        uint4 u;
        u.x = *reinterpret_cast<uint32_t*>(&h0);
        u.y = *reinterpret_cast<uint32_t*>(&h1);
        u.z = *reinterpret_cast<uint32_t*>(&h2);
        u.w = *reinterpret_cast<uint32_t*>(&h3);
        reinterpret_cast<uint4*>(outp)[(size_t)node * 32 + lane] = u;
    } else {
        float4* op = reinterpret_cast<float4*>(outp) + (size_t)node * 64 + lane * 2;
        op[0] = make_float4(o[0], o[1], o[2], o[3]);
        op[1] = make_float4(o[4], o[5], o[6], o[7]);
    }
}

// ---------------------------------------------------------------------------
extern "C" void kernel_launch(void* const* d_in, const int* in_sizes, int n_in,
                              void* d_out, int out_size)
{
    const float* x  = (const float*)d_in[0];
    const int*   ei = (const int*)  d_in[1];
    const float* W1 = (const float*)d_in[2];
    const float* b1 = (const float*)d_in[3];
    const float* W2 = (const float*)d_in[4];
    const float* b2 = (const float*)d_in[5];
    (void)in_sizes; (void)n_in; (void)out_size;

    const int* src = ei;
    const int* dst = ei + NEDGES;

    __half *hsh, *h1h, *wt1, *wt2;
    int* degp;
    cudaGetSymbolAddress((void**)&hsh, g_hsh);
    cudaGetSymbolAddress((void**)&h1h, g_h1h);
    cudaGetSymbolAddress((void**)&wt1, g_WT1);
    cudaGetSymbolAddress((void**)&wt2, g_WT2);
    cudaGetSymbolAddress((void**)&degp, g_deg);

    // Side stream + events for fork/join inside graph capture.
    static cudaStream_t sB = nullptr;
    static cudaEvent_t evFork = nullptr, evJoin = nullptr;
    if (!sB) {
        cudaStreamCreateWithFlags(&sB, cudaStreamNonBlocking);
        cudaEventCreateWithFlags(&evFork, cudaEventDisableTiming);
        cudaEventCreateWithFlags(&evJoin, cudaEventDisableTiming);
    }

    const dim3 gemm_grid(CDIM / BN, (NNODES + BM - 1) / BM);   // (2, 391)
    const int agg_grid = (NNODES + 7) / 8;

    // Fork side stream off the main (capturing) stream.
    cudaEventRecord(evFork, 0);
    cudaStreamWaitEvent(sB, evFork, 0);

    // Main: weight prep + GEMM1 (reads x fp32 directly).  Side: CSR prep.
    prep_w_k<<<(PREP_W + 255) / 256, 256>>>(W1, W2);                           // 0 main
    zero_int_k<<<(NNODES + 255) / 256, 256, 0, sB>>>(degp, NNODES);            // 1 side
    degree_k  <<<(NEDGES / 4 + 255) / 256, 256, 0, sB>>>(dst, NEDGES / 4);     // 2 side
    gemm_mma_k<true><<<gemm_grid, 256>>>(x, wt1, hsh, NNODES, FIN);            // 3 main <- ncu
    dinv_k    <<<(NNODES + 255) / 256, 256, 0, sB>>>(NNODES);                  // 4 side
    scan_k    <<<1, 1024, 0, sB>>>();                                          // 5 side
    csr_fill_k<<<(NEDGES + 255) / 256, 256, 0, sB>>>(src, dst, NEDGES);        // 6 side

    // Join: agg1 needs CSR + dinv + hsh.
    cudaEventRecord(evJoin, sB);
    cudaStreamWaitEvent(0, evJoin, 0);

    agg_k<<<agg_grid, 256>>>(b1, h1h, 1);                                      // 7
    gemm_mma_k<false><<<gemm_grid, 256>>>(h1h, wt2, hsh, NNODES, CDIM);        // 8
    agg_k<<<agg_grid, 256>>>(b2, d_out, 0);                                    // 9
}